// round 2
// baseline (speedup 1.0000x reference)
#include <cuda_runtime.h>
#include <math.h>

#define N_ROWS  131072
#define S_DIM   64
#define H_DIM   128
#define K_CODES 512
#define A_DIM   8

#define TM       128     // rows per CTA
#define KT       128     // codes per score tile
#define NTHREADS 256

typedef unsigned long long u64;

// packed f32x2 helpers -------------------------------------------------------
__device__ __forceinline__ void fma2(u64 &c, u64 a, u64 b) {
    asm("fma.rn.f32x2 %0, %1, %2, %0;" : "+l"(c) : "l"(a), "l"(b));
}
__device__ __forceinline__ u64 dup2(float x) {
    u64 r; asm("mov.b64 %0, {%1, %1};" : "=l"(r) : "f"(x)); return r;
}
__device__ __forceinline__ u64 pk2(float x, float y) {
    u64 r; asm("mov.b64 %0, {%1, %2};" : "=l"(r) : "f"(x), "f"(y)); return r;
}
__device__ __forceinline__ float2 unpk(u64 v) {
    float2 f; asm("mov.b64 {%0, %1}, %2;" : "=f"(f.x), "=f"(f.y) : "l"(v)); return f;
}

// Precomputed per-code data (written by precompute_kernel each launch)
__device__ float g_ee[K_CODES];            // sum(e*e) per code (fp64-accurate)
__device__ float g_probs[K_CODES * A_DIM]; // softmax(e@Wa+ba)
__device__ float g_value[K_CODES];         // e@Wv+bv

// ---------------------------------------------------------------------------
// Kernel 1: per-code table. 512 threads total.
// ---------------------------------------------------------------------------
__global__ void precompute_kernel(const float* __restrict__ emb,
                                  const float* __restrict__ Wa,
                                  const float* __restrict__ ba,
                                  const float* __restrict__ Wv,
                                  const float* __restrict__ bv)
{
    int k = blockIdx.x * blockDim.x + threadIdx.x;
    if (k >= K_CODES) return;
    const float* e = emb + k * H_DIM;

    double ee = 0.0;
    float logit[A_DIM];
#pragma unroll
    for (int a = 0; a < A_DIM; a++) logit[a] = 0.0f;
    float val = 0.0f;

    for (int j = 0; j < H_DIM; j++) {
        float ej = e[j];
        ee += (double)ej * (double)ej;
#pragma unroll
        for (int a = 0; a < A_DIM; a++)
            logit[a] = fmaf(ej, Wa[j * A_DIM + a], logit[a]);
        val = fmaf(ej, Wv[j], val);
    }
#pragma unroll
    for (int a = 0; a < A_DIM; a++) logit[a] += ba[a];
    val += bv[0];

    g_ee[k] = (float)ee;
    g_value[k] = val;

    // softmax (temperature = 1.0)
    float m = logit[0];
#pragma unroll
    for (int a = 1; a < A_DIM; a++) m = fmaxf(m, logit[a]);
    float p[A_DIM];
    float s = 0.0f;
#pragma unroll
    for (int a = 0; a < A_DIM; a++) { p[a] = expf(logit[a] - m); s += p[a]; }
#pragma unroll
    for (int a = 0; a < A_DIM; a++) g_probs[k * A_DIM + a] = p[a] / s;
}

// ---------------------------------------------------------------------------
// Kernel 2: fused encoder + VQ argmin + table lookup. f32x2 packed inner loops.
// SMEM layout (floats):
//   [0      .. 16384) sX1T : x1 transposed [H][TM]; later vv[128] + reduction
//   [16384  .. 32768) sX2T : x2 transposed [H][TM]
//   [32768  .. 49664) sBig : stage1 {sInT[64][128], sW1[64][128]},
//                            stage2 Wh[128][128], stage3 ET[128][132]
// ---------------------------------------------------------------------------
#define SMEM_FLOATS (32768 + 128 * 132)
#define SMEM_BYTES  (SMEM_FLOATS * 4)

__global__ __launch_bounds__(NTHREADS, 1)
void fused_kernel(const float* __restrict__ in,
                  const float* __restrict__ W1, const float* __restrict__ b1,
                  const float* __restrict__ Wh, const float* __restrict__ bh,
                  const float* __restrict__ emb,
                  float* __restrict__ out)
{
    extern __shared__ float sm[];
    float* sX1T = sm;
    float* sX2T = sm + 16384;
    float* sBig = sm + 32768;
    float* sInT = sBig;          // [64][128]
    float* sW1  = sBig + 8192;   // [64][128]
    float* sWh  = sBig;          // [128][128]
    float* sET  = sBig;          // [128][132] (pitch 132 keeps 16B alignment)

    const int tid = threadIdx.x;
    const int tx = tid & 15, ty = tid >> 4;
    const int c0 = tx * 8, r0 = ty * 8;
    const int rowBase = blockIdx.x * TM;

    // ---------------- Stage 0: load inputs (transposed) + W1 ----------------
    {
        const float4* gin = (const float4*)(in + (size_t)rowBase * S_DIM);
#pragma unroll
        for (int f = tid; f < TM * S_DIM / 4; f += NTHREADS) {  // 2048
            float4 v = gin[f];
            int row = f >> 4;          // (f*4)/64
            int s   = (f & 15) * 4;
            sInT[(s + 0) * TM + row] = v.x;
            sInT[(s + 1) * TM + row] = v.y;
            sInT[(s + 2) * TM + row] = v.z;
            sInT[(s + 3) * TM + row] = v.w;
        }
        const float4* gW1 = (const float4*)W1;
#pragma unroll
        for (int f = tid; f < S_DIM * H_DIM / 4; f += NTHREADS) // 2048
            ((float4*)sW1)[f] = gW1[f];
    }
    __syncthreads();

    // ---------------- Stage 1: x1 = relu(in@W1 + b1) ----------------
    {
        u64 acc[8][4];
#pragma unroll
        for (int i = 0; i < 8; i++)
#pragma unroll
            for (int j = 0; j < 4; j++) acc[i][j] = 0ULL;

#pragma unroll 4
        for (int d = 0; d < S_DIM; d++) {
            float4 a0 = *(const float4*)(sInT + d * TM + r0);
            float4 a1 = *(const float4*)(sInT + d * TM + r0 + 4);
            float4 bb0 = *(const float4*)(sW1 + d * H_DIM + c0);
            float4 bb1 = *(const float4*)(sW1 + d * H_DIM + c0 + 4);
            u64 ad[8] = {dup2(a0.x), dup2(a0.y), dup2(a0.z), dup2(a0.w),
                         dup2(a1.x), dup2(a1.y), dup2(a1.z), dup2(a1.w)};
            u64 bp[4] = {pk2(bb0.x, bb0.y), pk2(bb0.z, bb0.w),
                         pk2(bb1.x, bb1.y), pk2(bb1.z, bb1.w)};
#pragma unroll
            for (int i = 0; i < 8; i++)
#pragma unroll
                for (int j = 0; j < 4; j++)
                    fma2(acc[i][j], ad[i], bp[j]);
        }
#pragma unroll
        for (int j = 0; j < 4; j++) {
            float bj0 = b1[c0 + 2 * j];
            float bj1 = b1[c0 + 2 * j + 1];
#pragma unroll
            for (int i = 0; i < 8; i++) {
                float2 v = unpk(acc[i][j]);
                sX1T[(c0 + 2 * j + 0) * TM + (r0 + i)] = fmaxf(v.x + bj0, 0.0f);
                sX1T[(c0 + 2 * j + 1) * TM + (r0 + i)] = fmaxf(v.y + bj1, 0.0f);
            }
        }
    }
    __syncthreads();

    // ---------------- Load Wh (overwrites sInT/sW1) ----------------
    {
        const float4* gWh = (const float4*)Wh;
#pragma unroll
        for (int f = tid; f < H_DIM * H_DIM / 4; f += NTHREADS)  // 4096
            ((float4*)sWh)[f] = gWh[f];
    }
    __syncthreads();

    // ---------------- Stage 2: x2 = relu(x1@Wh + bh) ----------------
    {
        u64 acc[8][4];
#pragma unroll
        for (int i = 0; i < 8; i++)
#pragma unroll
            for (int j = 0; j < 4; j++) acc[i][j] = 0ULL;

#pragma unroll 4
        for (int d = 0; d < H_DIM; d++) {
            float4 a0 = *(const float4*)(sX1T + d * TM + r0);
            float4 a1 = *(const float4*)(sX1T + d * TM + r0 + 4);
            float4 bb0 = *(const float4*)(sWh + d * H_DIM + c0);
            float4 bb1 = *(const float4*)(sWh + d * H_DIM + c0 + 4);
            u64 ad[8] = {dup2(a0.x), dup2(a0.y), dup2(a0.z), dup2(a0.w),
                         dup2(a1.x), dup2(a1.y), dup2(a1.z), dup2(a1.w)};
            u64 bp[4] = {pk2(bb0.x, bb0.y), pk2(bb0.z, bb0.w),
                         pk2(bb1.x, bb1.y), pk2(bb1.z, bb1.w)};
#pragma unroll
            for (int i = 0; i < 8; i++)
#pragma unroll
                for (int j = 0; j < 4; j++)
                    fma2(acc[i][j], ad[i], bp[j]);
        }
#pragma unroll
        for (int j = 0; j < 4; j++) {
            float bj0 = bh[c0 + 2 * j];
            float bj1 = bh[c0 + 2 * j + 1];
#pragma unroll
            for (int i = 0; i < 8; i++) {
                float2 v = unpk(acc[i][j]);
                sX2T[(c0 + 2 * j + 0) * TM + (r0 + i)] = fmaxf(v.x + bj0, 0.0f);
                sX2T[(c0 + 2 * j + 1) * TM + (r0 + i)] = fmaxf(v.y + bj1, 0.0f);
            }
        }
    }
    __syncthreads();

    // ---------------- vv = ||x||^2 per row (sX1T now free) ----------------
    float* vv = sX1T;  // [128]
    if (tid < TM) {
        float s = 0.0f;
#pragma unroll 4
        for (int d = 0; d < H_DIM; d++) {
            float x = sX2T[d * TM + tid];
            s = fmaf(x, x, s);
        }
        vv[tid] = s;
    }
    __syncthreads();

    float vvr[8];
#pragma unroll
    for (int i = 0; i < 8; i++) vvr[i] = vv[r0 + i];

    float bestD[8];
    int bestI[8];
#pragma unroll
    for (int i = 0; i < 8; i++) { bestD[i] = __int_as_float(0x7f800000); bestI[i] = 0; }

    // ---------------- Stage 3: scores vs all 512 codes, 4 tiles ----------------
    for (int tile = 0; tile < K_CODES / KT; tile++) {
        // load E tile transposed into sET [d][code], pitch 132
        const float4* ge = (const float4*)(emb + (size_t)tile * KT * H_DIM);
#pragma unroll
        for (int f = tid; f < KT * H_DIM / 4; f += NTHREADS) {  // 4096
            float4 v = ge[f];
            int code = f >> 5;         // (f*4)/128
            int d    = (f & 31) * 4;
            sET[(d + 0) * 132 + code] = v.x;
            sET[(d + 1) * 132 + code] = v.y;
            sET[(d + 2) * 132 + code] = v.z;
            sET[(d + 3) * 132 + code] = v.w;
        }
        __syncthreads();

        u64 acc[8][4];
#pragma unroll
        for (int i = 0; i < 8; i++)
#pragma unroll
            for (int j = 0; j < 4; j++) acc[i][j] = 0ULL;

#pragma unroll 4
        for (int d = 0; d < H_DIM; d++) {
            float4 a0 = *(const float4*)(sX2T + d * TM + r0);
            float4 a1 = *(const float4*)(sX2T + d * TM + r0 + 4);
            float4 bb0 = *(const float4*)(sET + d * 132 + c0);
            float4 bb1 = *(const float4*)(sET + d * 132 + c0 + 4);
            u64 ad[8] = {dup2(a0.x), dup2(a0.y), dup2(a0.z), dup2(a0.w),
                         dup2(a1.x), dup2(a1.y), dup2(a1.z), dup2(a1.w)};
            u64 bp[4] = {pk2(bb0.x, bb0.y), pk2(bb0.z, bb0.w),
                         pk2(bb1.x, bb1.y), pk2(bb1.z, bb1.w)};
#pragma unroll
            for (int i = 0; i < 8; i++)
#pragma unroll
                for (int j = 0; j < 4; j++)
                    fma2(acc[i][j], ad[i], bp[j]);
        }

        int codeBase = tile * KT + c0;
#pragma unroll
        for (int j = 0; j < 4; j++) {
            float ee0 = g_ee[codeBase + 2 * j];
            float ee1 = g_ee[codeBase + 2 * j + 1];
#pragma unroll
            for (int i = 0; i < 8; i++) {
                float2 dot = unpk(acc[i][j]);
                // faithful to reference: d = (vv - 2*dot) + ee, no FMA fusion
                float dd0 = __fadd_rn(__fsub_rn(vvr[i], __fmul_rn(2.0f, dot.x)), ee0);
                float dd1 = __fadd_rn(__fsub_rn(vvr[i], __fmul_rn(2.0f, dot.y)), ee1);
                if (dd0 < bestD[i]) { bestD[i] = dd0; bestI[i] = codeBase + 2 * j; }
                if (dd1 < bestD[i]) { bestD[i] = dd1; bestI[i] = codeBase + 2 * j + 1; }
            }
        }
        __syncthreads();
    }

    // ---------------- Cross-thread argmin reduction + output ----------------
    float* redD = sX1T + 128;                 // [128][16]
    int*   redI = (int*)(sX1T + 128 + TM * 16);
#pragma unroll
    for (int i = 0; i < 8; i++) {
        redD[(r0 + i) * 16 + tx] = bestD[i];
        redI[(r0 + i) * 16 + tx] = bestI[i];
    }
    __syncthreads();

    if (tid < TM) {
        float best = redD[tid * 16];
        int bi = redI[tid * 16];
#pragma unroll
        for (int t = 1; t < 16; t++) {
            float v = redD[tid * 16 + t];
            int id = redI[tid * 16 + t];
            if (v < best || (v == best && id < bi)) { best = v; bi = id; }
        }
        int gr = rowBase + tid;
        float4 p0 = *(const float4*)(g_probs + bi * A_DIM);
        float4 p1 = *(const float4*)(g_probs + bi * A_DIM + 4);
        float4* po = (float4*)out;
        po[gr * 2 + 0] = p0;
        po[gr * 2 + 1] = p1;
        out[(size_t)N_ROWS * A_DIM + gr] = g_value[bi];
    }
}

// ---------------------------------------------------------------------------
extern "C" void kernel_launch(void* const* d_in, const int* in_sizes, int n_in,
                              void* d_out, int out_size)
{
    const float* inputs = (const float*)d_in[0];
    const float* W1  = (const float*)d_in[1];
    const float* b1  = (const float*)d_in[2];
    const float* Wh  = (const float*)d_in[3];
    const float* bh  = (const float*)d_in[4];
    const float* emb = (const float*)d_in[5];
    const float* Wa  = (const float*)d_in[6];
    const float* ba  = (const float*)d_in[7];
    const float* Wv  = (const float*)d_in[8];
    const float* bv  = (const float*)d_in[9];

    cudaFuncSetAttribute(fused_kernel,
                         cudaFuncAttributeMaxDynamicSharedMemorySize, SMEM_BYTES);

    precompute_kernel<<<2, 256>>>(emb, Wa, ba, Wv, bv);
    fused_kernel<<<N_ROWS / TM, NTHREADS, SMEM_BYTES>>>(
        inputs, W1, b1, Wh, bh, emb, (float*)d_out);
}

// round 4
// speedup vs baseline: 2.0384x; 2.0384x over previous
#include <cuda_runtime.h>
#include <cuda_fp16.h>
#include <math.h>
#include <stdint.h>

#define N_ROWS  131072
#define S_DIM   64
#define H_DIM   128
#define K_CODES 512
#define A_DIM   8
#define TM      128
#define NTHREADS 256
#define MARGIN  1e-3f

typedef uint32_t u32;

// ===================== warp-level tensor ops (base PTX, no 'a' features) ====
#define LDSM4(r, addr)                                                        \
    asm volatile("ldmatrix.sync.aligned.m8n8.x4.shared.b16 {%0,%1,%2,%3}, [%4];" \
                 : "=r"((r)[0]), "=r"((r)[1]), "=r"((r)[2]), "=r"((r)[3])     \
                 : "r"(addr))

__device__ __forceinline__ void mma16816(float* c, const u32* a, u32 b0, u32 b1) {
    asm volatile("mma.sync.aligned.m16n8k16.row.col.f32.f16.f16.f32 "
                 "{%0,%1,%2,%3}, {%4,%5,%6,%7}, {%8,%9}, {%0,%1,%2,%3};"
                 : "+f"(c[0]), "+f"(c[1]), "+f"(c[2]), "+f"(c[3])
                 : "r"(a[0]), "r"(a[1]), "r"(a[2]), "r"(a[3]), "r"(b0), "r"(b1));
}

__device__ __forceinline__ u32 smem_u32(const void* p) {
    u32 a; asm("{ .reg .u64 t; cvta.to.shared.u64 t, %1; cvt.u32.u64 %0, t; }"
               : "=r"(a) : "l"(p)); return a;
}
__device__ __forceinline__ u32 pkh(float a, float b) {
    __half2 t; t.x = __float2half_rn(a); t.y = __float2half_rn(b);
    return *reinterpret_cast<u32*>(&t);
}

// ===================== device globals =====================
__device__ float g_ee[K_CODES];
__device__ float g_probs[K_CODES * A_DIM];
__device__ float g_value[K_CODES];

// fp16 hi/lo weight & codebook images (prepacked by prep_weights):
//  W1T: [n=128][k=64] pitch 72 halves, hi then lo        -> 2 * 9216
//  WhT: [n=128][k=128] pitch 136 halves, hi then lo      -> 2 * 17408
//  E:   4 tiles x { [c=128][d=128] pitch 136 hi, lo }    -> 4 * 2 * 17408
#define IMG_W1 0
#define IMG_WH 18432
#define IMG_E  53248
#define IMG_TOTAL 192512
__device__ __half g_img[IMG_TOTAL];

// ===================== kernel 1: per-code tables =====================
__global__ void precompute_tables(const float* __restrict__ emb,
                                  const float* __restrict__ Wa, const float* __restrict__ ba,
                                  const float* __restrict__ Wv, const float* __restrict__ bv)
{
    int k = blockIdx.x * blockDim.x + threadIdx.x;
    if (k >= K_CODES) return;
    const float* e = emb + k * H_DIM;
    double ee = 0.0;
    float logit[A_DIM];
#pragma unroll
    for (int a = 0; a < A_DIM; a++) logit[a] = 0.0f;
    float val = 0.0f;
    for (int j = 0; j < H_DIM; j++) {
        float ej = e[j];
        ee += (double)ej * (double)ej;
#pragma unroll
        for (int a = 0; a < A_DIM; a++) logit[a] = fmaf(ej, Wa[j * A_DIM + a], logit[a]);
        val = fmaf(ej, Wv[j], val);
    }
#pragma unroll
    for (int a = 0; a < A_DIM; a++) logit[a] += ba[a];
    val += bv[0];
    g_ee[k] = (float)ee;
    g_value[k] = val;
    float m = logit[0];
#pragma unroll
    for (int a = 1; a < A_DIM; a++) m = fmaxf(m, logit[a]);
    float p[A_DIM], s = 0.0f;
#pragma unroll
    for (int a = 0; a < A_DIM; a++) { p[a] = expf(logit[a] - m); s += p[a]; }
#pragma unroll
    for (int a = 0; a < A_DIM; a++) g_probs[k * A_DIM + a] = p[a] / s;
}

// ===================== kernel 2: weight/codebook hi-lo images ===============
__global__ void prep_weights(const float* __restrict__ W1, const float* __restrict__ Wh,
                             const float* __restrict__ emb)
{
    int idx = blockIdx.x * blockDim.x + threadIdx.x;   // 90112 total
    if (idx < 8192) {                       // W1T: n=h (0..127), k=s (0..63)
        int n = idx >> 6, s = idx & 63;
        float v = W1[s * H_DIM + n];
        __half h = __float2half_rn(v);
        __half l = __float2half_rn(v - __half2float(h));
        int o = n * 72 + s;
        g_img[IMG_W1 + o] = h;
        g_img[IMG_W1 + 9216 + o] = l;
    } else if (idx < 24576) {               // WhT: n (0..127), k (0..127)
        int j = idx - 8192;
        int n = j >> 7, k = j & 127;
        float v = Wh[k * H_DIM + n];
        __half h = __float2half_rn(v);
        __half l = __float2half_rn(v - __half2float(h));
        int o = n * 136 + k;
        g_img[IMG_WH + o] = h;
        g_img[IMG_WH + 17408 + o] = l;
    } else if (idx < 90112) {               // E: code g (0..511), dim d
        int j = idx - 24576;
        int g = j >> 7, d = j & 127;
        int t = g >> 7, c = g & 127;
        float v = emb[g * H_DIM + d];
        __half h = __float2half_rn(v);
        __half l = __float2half_rn(v - __half2float(h));
        int o = c * 136 + d;
        g_img[IMG_E + t * 34816 + o] = h;
        g_img[IMG_E + t * 34816 + 17408 + o] = l;
    }
}

// ===================== kernel 3: fused main =====================
// SMEM byte map:
#define OFF_B1   0        // float[128]
#define OFF_BH   512      // float[128]
#define OFF_VV   1024     // float[128]
#define OFF_EE   1536     // float[512]
#define OFF_CD   3584     // float[128][8]
#define OFF_CI   7680     // int[128][8]
#define Z_A64    11776    // 36864 B: input hi | lo(+18432)   (pitch 144 B)
#define Z_B64    48640    // 36864 B: W1 hi | lo(+18432)      (pitch 144 B)
#define Z_A128   85504    // 69632 B: x1 hi | lo(+34816)      (pitch 272 B)
#define Z_B128   155136   // 69632 B: Wh / E tiles hi | lo(+34816)
#define SMEM_BYTES 224768
// x2 image lives in Z_A64 region (hi at Z_A64, lo at Z_A64+34816) after stage 2.

// 3-pass split GEMM: acc += Ah*Bh + Ah*Bl + Al*Bh   (C 128x128, warp = 16 rows)
__device__ __forceinline__ void run_gemm(int ksteps, u32 aH, u32 aL, u32 bH, u32 bL,
                                         int pitchA, int pitchB,
                                         int lane, int wrow, float (*acc)[4])
{
    const u32 aoff = (u32)(wrow + (lane & 15)) * pitchA + (u32)(lane >> 4) * 16;
    const u32 boff = (u32)((lane & 7) + ((lane >> 4) << 3)) * pitchB
                   + (u32)((lane >> 3) & 1) * 16;
    for (int ks = 0; ks < ksteps; ks++) {
        u32 ah[4], al[4];
        LDSM4(ah, aH + aoff + ks * 32);
        LDSM4(al, aL + aoff + ks * 32);
#pragma unroll
        for (int bt = 0; bt < 8; bt++) {
            u32 bh[4], bl[4];
            LDSM4(bh, bH + boff + (u32)bt * 16 * pitchB + ks * 32);
            mma16816(acc[2 * bt],     ah, bh[0], bh[1]);
            mma16816(acc[2 * bt + 1], ah, bh[2], bh[3]);
            mma16816(acc[2 * bt],     al, bh[0], bh[1]);
            mma16816(acc[2 * bt + 1], al, bh[2], bh[3]);
            LDSM4(bl, bL + boff + (u32)bt * 16 * pitchB + ks * 32);
            mma16816(acc[2 * bt],     ah, bl[0], bl[1]);
            mma16816(acc[2 * bt + 1], ah, bl[2], bl[3]);
        }
    }
}

__global__ __launch_bounds__(NTHREADS, 1)
void fused_kernel(const float* __restrict__ in,
                  const float* __restrict__ b1, const float* __restrict__ bh,
                  const float* __restrict__ emb,
                  float* __restrict__ out)
{
    extern __shared__ __align__(16) unsigned char smem[];
    const u32 sb = smem_u32(smem);
    char* sc = (char*)smem;

    const int tid  = threadIdx.x;
    const int wid  = tid >> 5;
    const int lane = tid & 31;
    const int g    = lane >> 2;      // row group within warp tile
    const int q    = lane & 3;       // col group
    const int wrow = wid * 16;       // warp's first C row
    const int r1 = wrow + g, r2 = r1 + 8;
    const int rowBase = blockIdx.x * TM;

    float* sB1 = (float*)(sc + OFF_B1);
    float* sBH = (float*)(sc + OFF_BH);
    float* sVV = (float*)(sc + OFF_VV);
    float* sEE = (float*)(sc + OFF_EE);
    float* sCD = (float*)(sc + OFF_CD);
    int*   sCI = (int*)  (sc + OFF_CI);

    // ---------------- Stage 0 fills ----------------
    {
        // W1 images -> Z_B64 (2304 float4)
        const float4* s0 = (const float4*)(g_img + IMG_W1);
        float4* d0 = (float4*)(sc + Z_B64);
#pragma unroll
        for (int i = tid; i < 2304; i += NTHREADS) d0[i] = s0[i];
        // Wh images -> Z_B128 (4352 float4)
        const float4* s1 = (const float4*)(g_img + IMG_WH);
        float4* d1 = (float4*)(sc + Z_B128);
#pragma unroll
        for (int i = tid; i < 4352; i += NTHREADS) d1[i] = s1[i];
        // input tile split -> Z_A64 (pitch 144 B), hi | lo(+18432)
        for (int p = tid; p < 128 * 32; p += NTHREADS) {
            int row = p >> 5, pc = p & 31;
            float2 v = *(const float2*)(in + (size_t)(rowBase + row) * S_DIM + 2 * pc);
            __half h0 = __float2half_rn(v.x);
            __half h1 = __float2half_rn(v.y);
            float l0 = v.x - __half2float(h0);
            float l1 = v.y - __half2float(h1);
            u32 o = (u32)row * 144 + (u32)pc * 4;
            *(u32*)(sc + Z_A64 + o)         = pkh(__half2float(h0), __half2float(h1));
            *(u32*)(sc + Z_A64 + 18432 + o) = pkh(l0, l1);
        }
        if (tid < 128) { sB1[tid] = b1[tid]; sBH[tid] = bh[tid]; }
        for (int i = tid; i < 512; i += NTHREADS) sEE[i] = g_ee[i];
    }
    __syncthreads();

    float acc[16][4];

    // ---------------- Stage 1: x1 = relu(in @ W1 + b1) ----------------
#pragma unroll
    for (int t = 0; t < 16; t++)
#pragma unroll
        for (int j = 0; j < 4; j++) acc[t][j] = 0.0f;
    run_gemm(4, sb + Z_A64, sb + Z_A64 + 18432, sb + Z_B64, sb + Z_B64 + 18432,
             144, 144, lane, wrow, acc);
#pragma unroll
    for (int t = 0; t < 16; t++) {
        int c = 8 * t + 2 * q;
        float z0 = fmaxf(acc[t][0] + sB1[c],     0.0f);
        float z1 = fmaxf(acc[t][1] + sB1[c + 1], 0.0f);
        float z2 = fmaxf(acc[t][2] + sB1[c],     0.0f);
        float z3 = fmaxf(acc[t][3] + sB1[c + 1], 0.0f);
        __half h0 = __float2half_rn(z0), h1 = __float2half_rn(z1);
        __half h2 = __float2half_rn(z2), h3 = __float2half_rn(z3);
        u32 o1 = (u32)r1 * 272 + (u32)c * 2;
        u32 o2 = (u32)r2 * 272 + (u32)c * 2;
        *(u32*)(sc + Z_A128 + o1)         = pkh(__half2float(h0), __half2float(h1));
        *(u32*)(sc + Z_A128 + o2)         = pkh(__half2float(h2), __half2float(h3));
        *(u32*)(sc + Z_A128 + 34816 + o1) = pkh(z0 - __half2float(h0), z1 - __half2float(h1));
        *(u32*)(sc + Z_A128 + 34816 + o2) = pkh(z2 - __half2float(h2), z3 - __half2float(h3));
    }
    __syncthreads();

    // ---------------- Stage 2: x2 = relu(x1 @ Wh + bh) ----------------
#pragma unroll
    for (int t = 0; t < 16; t++)
#pragma unroll
        for (int j = 0; j < 4; j++) acc[t][j] = 0.0f;
    run_gemm(8, sb + Z_A128, sb + Z_A128 + 34816, sb + Z_B128, sb + Z_B128 + 34816,
             272, 272, lane, wrow, acc);
    {
        float vp1 = 0.0f, vp2 = 0.0f;
#pragma unroll
        for (int t = 0; t < 16; t++) {
            int c = 8 * t + 2 * q;
            float z0 = fmaxf(acc[t][0] + sBH[c],     0.0f);
            float z1 = fmaxf(acc[t][1] + sBH[c + 1], 0.0f);
            float z2 = fmaxf(acc[t][2] + sBH[c],     0.0f);
            float z3 = fmaxf(acc[t][3] + sBH[c + 1], 0.0f);
            __half h0 = __float2half_rn(z0), h1 = __float2half_rn(z1);
            __half h2 = __float2half_rn(z2), h3 = __float2half_rn(z3);
            float fl0 = z0 - __half2float(h0), fl1 = z1 - __half2float(h1);
            float fl2 = z2 - __half2float(h2), fl3 = z3 - __half2float(h3);
            // effective x = hi + lo (what MMA & recheck consume)
            float x0 = __half2float(h0) + __half2float(__float2half_rn(fl0));
            float x1 = __half2float(h1) + __half2float(__float2half_rn(fl1));
            float x2 = __half2float(h2) + __half2float(__float2half_rn(fl2));
            float x3 = __half2float(h3) + __half2float(__float2half_rn(fl3));
            vp1 = fmaf(x0, x0, vp1); vp1 = fmaf(x1, x1, vp1);
            vp2 = fmaf(x2, x2, vp2); vp2 = fmaf(x3, x3, vp2);
            u32 o1 = (u32)r1 * 272 + (u32)c * 2;
            u32 o2 = (u32)r2 * 272 + (u32)c * 2;
            *(u32*)(sc + Z_A64 + o1)         = pkh(__half2float(h0), __half2float(h1));
            *(u32*)(sc + Z_A64 + o2)         = pkh(__half2float(h2), __half2float(h3));
            *(u32*)(sc + Z_A64 + 34816 + o1) = pkh(fl0, fl1);
            *(u32*)(sc + Z_A64 + 34816 + o2) = pkh(fl2, fl3);
        }
        // reduce vv across the 4 q-lanes of each row
        vp1 += __shfl_xor_sync(0xFFFFFFFF, vp1, 1);
        vp1 += __shfl_xor_sync(0xFFFFFFFF, vp1, 2);
        vp2 += __shfl_xor_sync(0xFFFFFFFF, vp2, 1);
        vp2 += __shfl_xor_sync(0xFFFFFFFF, vp2, 2);
        if (q == 0) { sVV[r1] = vp1; sVV[r2] = vp2; }
    }
    __syncthreads();

    // ---------------- Score: 4 tiles x (fill E, 3-pass MMA, top-2 scan) -------
    const float vv1 = sVV[r1], vv2 = sVV[r2];
    float b1d1 = __int_as_float(0x7f800000), b2d1 = b1d1;
    float b1d2 = b1d1, b2d2 = b1d1;
    int b1i1 = 0, b2i1 = 0, b1i2 = 0, b2i2 = 0;

    for (int tile = 0; tile < 4; tile++) {
        {   // E tile images -> Z_B128
            const float4* s0 = (const float4*)(g_img + IMG_E + tile * 34816);
            float4* d0 = (float4*)(sc + Z_B128);
#pragma unroll
            for (int i = tid; i < 4352; i += NTHREADS) d0[i] = s0[i];
        }
        __syncthreads();

#pragma unroll
        for (int t = 0; t < 16; t++)
#pragma unroll
            for (int j = 0; j < 4; j++) acc[t][j] = 0.0f;
        run_gemm(8, sb + Z_A64, sb + Z_A64 + 34816, sb + Z_B128, sb + Z_B128 + 34816,
                 272, 272, lane, wrow, acc);

        int codeBase = tile * 128;
#pragma unroll
        for (int t = 0; t < 16; t++) {
            int c = 8 * t + 2 * q;
#pragma unroll
            for (int jj = 0; jj < 2; jj++) {
                int code = codeBase + c + jj;
                float ee = sEE[code];
                float d1 = fmaf(-2.0f, acc[t][jj],     vv1) + ee;
                float d2 = fmaf(-2.0f, acc[t][2 + jj], vv2) + ee;
                if (d1 < b1d1) { b2d1 = b1d1; b2i1 = b1i1; b1d1 = d1; b1i1 = code; }
                else if (d1 < b2d1) { b2d1 = d1; b2i1 = code; }
                if (d2 < b1d2) { b2d2 = b1d2; b2i2 = b1i2; b1d2 = d2; b1i2 = code; }
                else if (d2 < b2d2) { b2d2 = d2; b2i2 = code; }
            }
        }
        __syncthreads();
    }

    // ---------------- candidates + exact fp32 re-check + output ----------------
    sCD[r1 * 8 + q * 2]     = b1d1;  sCI[r1 * 8 + q * 2]     = b1i1;
    sCD[r1 * 8 + q * 2 + 1] = b2d1;  sCI[r1 * 8 + q * 2 + 1] = b2i1;
    sCD[r2 * 8 + q * 2]     = b1d2;  sCI[r2 * 8 + q * 2]     = b1i2;
    sCD[r2 * 8 + q * 2 + 1] = b2d2;  sCI[r2 * 8 + q * 2 + 1] = b2i2;
    __syncthreads();

    if (tid < TM) {
        int row = tid;
        float cd[8]; int ci[8];
#pragma unroll
        for (int j = 0; j < 8; j++) { cd[j] = sCD[row * 8 + j]; ci[j] = sCI[row * 8 + j]; }
        float mn = cd[0];
#pragma unroll
        for (int j = 1; j < 8; j++) mn = fminf(mn, cd[j]);
        int cnt = 0; int cidx[8];
#pragma unroll
        for (int j = 0; j < 8; j++)
            if (cd[j] <= mn + MARGIN) cidx[cnt++] = ci[j];

        float dots[8];
#pragma unroll
        for (int j = 0; j < 8; j++) dots[j] = 0.0f;
        float vx = 0.0f;
        // rotated column order: conflict-free LDS, consistent across candidates
        for (int i = 0; i < 64; i++) {
            int w = (row + i) & 63;                 // u32 word index -> cols 2w, 2w+1
            u32 hw = *(const u32*)(sc + Z_A64 + (u32)row * 272 + (u32)w * 4);
            u32 lw = *(const u32*)(sc + Z_A64 + 34816 + (u32)row * 272 + (u32)w * 4);
            __half2 hh = *reinterpret_cast<__half2*>(&hw);
            __half2 ll = *reinterpret_cast<__half2*>(&lw);
            float x0 = __half2float(hh.x) + __half2float(ll.x);
            float x1 = __half2float(hh.y) + __half2float(ll.y);
            vx = fmaf(x0, x0, vx);
            vx = fmaf(x1, x1, vx);
            for (int j = 0; j < cnt; j++) {
                const float* ep = emb + (size_t)cidx[j] * H_DIM + 2 * w;
                dots[j] = fmaf(x0, __ldg(ep),     dots[j]);
                dots[j] = fmaf(x1, __ldg(ep + 1), dots[j]);
            }
        }
        float bestD = __int_as_float(0x7f800000);
        int bestI = 0x7fffffff;
        for (int j = 0; j < cnt; j++) {
            float dd = __fadd_rn(__fsub_rn(vx, __fmul_rn(2.0f, dots[j])), sEE[cidx[j]]);
            if (dd < bestD || (dd == bestD && cidx[j] < bestI)) { bestD = dd; bestI = cidx[j]; }
        }

        int gr = rowBase + row;
        float4 p0 = *(const float4*)(g_probs + bestI * A_DIM);
        float4 p1 = *(const float4*)(g_probs + bestI * A_DIM + 4);
        float4* po = (float4*)out;
        po[gr * 2 + 0] = p0;
        po[gr * 2 + 1] = p1;
        out[(size_t)N_ROWS * A_DIM + gr] = g_value[bestI];
    }
}

// ===================== launch =====================
extern "C" void kernel_launch(void* const* d_in, const int* in_sizes, int n_in,
                              void* d_out, int out_size)
{
    const float* inputs = (const float*)d_in[0];
    const float* W1  = (const float*)d_in[1];
    const float* b1  = (const float*)d_in[2];
    const float* Wh  = (const float*)d_in[3];
    const float* bh  = (const float*)d_in[4];
    const float* emb = (const float*)d_in[5];
    const float* Wa  = (const float*)d_in[6];
    const float* ba  = (const float*)d_in[7];
    const float* Wv  = (const float*)d_in[8];
    const float* bv  = (const float*)d_in[9];

    cudaFuncSetAttribute(fused_kernel,
                         cudaFuncAttributeMaxDynamicSharedMemorySize, SMEM_BYTES);

    precompute_tables<<<2, 256>>>(emb, Wa, ba, Wv, bv);
    prep_weights<<<352, 256>>>(W1, Wh, emb);
    fused_kernel<<<N_ROWS / TM, NTHREADS, SMEM_BYTES>>>(
        inputs, b1, bh, emb, (float*)d_out);
}

// round 5
// speedup vs baseline: 3.1219x; 1.5316x over previous
#include <cuda_runtime.h>
#include <cuda_fp16.h>
#include <math.h>
#include <stdint.h>

#define N_ROWS  131072
#define S_DIM   64
#define H_DIM   128
#define K_CODES 512
#define A_DIM   8
#define TM      128
#define NTHREADS 512
#define MARGIN  1e-3f

typedef uint32_t u32;

// ===================== warp-level tensor ops (base PTX) =====================
#define LDSM4(r, addr)                                                        \
    asm volatile("ldmatrix.sync.aligned.m8n8.x4.shared.b16 {%0,%1,%2,%3}, [%4];" \
                 : "=r"((r)[0]), "=r"((r)[1]), "=r"((r)[2]), "=r"((r)[3])     \
                 : "r"(addr))

__device__ __forceinline__ void mma16816(float* c, const u32* a, u32 b0, u32 b1) {
    asm volatile("mma.sync.aligned.m16n8k16.row.col.f32.f16.f16.f32 "
                 "{%0,%1,%2,%3}, {%4,%5,%6,%7}, {%8,%9}, {%0,%1,%2,%3};"
                 : "+f"(c[0]), "+f"(c[1]), "+f"(c[2]), "+f"(c[3])
                 : "r"(a[0]), "r"(a[1]), "r"(a[2]), "r"(a[3]), "r"(b0), "r"(b1));
}

__device__ __forceinline__ u32 smem_u32(const void* p) {
    u32 a; asm("{ .reg .u64 t; cvta.to.shared.u64 t, %1; cvt.u32.u64 %0, t; }"
               : "=r"(a) : "l"(p)); return a;
}
__device__ __forceinline__ u32 pkh(float a, float b) {
    __half2 t; t.x = __float2half_rn(a); t.y = __float2half_rn(b);
    return *reinterpret_cast<u32*>(&t);
}
__device__ __forceinline__ void cpa16(u32 dst, const void* src) {
    asm volatile("cp.async.cg.shared.global [%0], [%1], 16;"
                 :: "r"(dst), "l"(src) : "memory");
}
#define CP_COMMIT() asm volatile("cp.async.commit_group;" ::: "memory")
#define CP_WAIT(n)  asm volatile("cp.async.wait_group %0;" :: "n"(n) : "memory")

// ===================== device globals =====================
__device__ float g_ee[K_CODES];
__device__ float g_probs[K_CODES * A_DIM];
__device__ float g_value[K_CODES];

// fp16 hi/lo weight & codebook images:
//  W1T: [n=128][k=64] pitch 72 halves, hi then lo        -> 2 * 9216
//  WhT: [n=128][k=128] pitch 136 halves, hi then lo      -> 2 * 17408
//  E:   4 tiles x { [c=128][d=128] pitch 136 hi, lo }
#define IMG_W1 0
#define IMG_WH 18432
#define IMG_E  53248
#define IMG_TOTAL 192512
__device__ __half g_img[IMG_TOTAL];

// ===================== kernel 1: per-code tables (warp per code) ============
__global__ void precompute_tables(const float* __restrict__ emb,
                                  const float* __restrict__ Wa, const float* __restrict__ ba,
                                  const float* __restrict__ Wv, const float* __restrict__ bv)
{
    int code = (blockIdx.x * blockDim.x + threadIdx.x) >> 5;
    int lane = threadIdx.x & 31;
    if (code >= K_CODES) return;
    const float* e = emb + code * H_DIM;

    double ee = 0.0;
    float logit[A_DIM];
#pragma unroll
    for (int a = 0; a < A_DIM; a++) logit[a] = 0.0f;
    float val = 0.0f;
#pragma unroll
    for (int j = 0; j < 4; j++) {
        int d = lane + 32 * j;
        float ej = e[d];
        ee += (double)ej * (double)ej;
#pragma unroll
        for (int a = 0; a < A_DIM; a++) logit[a] = fmaf(ej, Wa[d * A_DIM + a], logit[a]);
        val = fmaf(ej, Wv[d], val);
    }
#pragma unroll
    for (int off = 16; off; off >>= 1) {
        ee  += __shfl_xor_sync(0xFFFFFFFFu, ee,  off);
        val += __shfl_xor_sync(0xFFFFFFFFu, val, off);
#pragma unroll
        for (int a = 0; a < A_DIM; a++)
            logit[a] += __shfl_xor_sync(0xFFFFFFFFu, logit[a], off);
    }
    if (lane == 0) {
#pragma unroll
        for (int a = 0; a < A_DIM; a++) logit[a] += ba[a];
        g_ee[code] = (float)ee;
        g_value[code] = val + bv[0];
        float m = logit[0];
#pragma unroll
        for (int a = 1; a < A_DIM; a++) m = fmaxf(m, logit[a]);
        float p[A_DIM], s = 0.0f;
#pragma unroll
        for (int a = 0; a < A_DIM; a++) { p[a] = expf(logit[a] - m); s += p[a]; }
#pragma unroll
        for (int a = 0; a < A_DIM; a++) g_probs[code * A_DIM + a] = p[a] / s;
    }
}

// ===================== kernel 2: weight/codebook hi-lo images ===============
__global__ void prep_weights(const float* __restrict__ W1, const float* __restrict__ Wh,
                             const float* __restrict__ emb)
{
    int idx = blockIdx.x * blockDim.x + threadIdx.x;
    if (idx < 8192) {                       // W1T
        int n = idx >> 6, s = idx & 63;
        float v = W1[s * H_DIM + n];
        __half h = __float2half_rn(v);
        __half l = __float2half_rn(v - __half2float(h));
        int o = n * 72 + s;
        g_img[IMG_W1 + o] = h;
        g_img[IMG_W1 + 9216 + o] = l;
    } else if (idx < 24576) {               // WhT
        int j = idx - 8192;
        int n = j >> 7, k = j & 127;
        float v = Wh[k * H_DIM + n];
        __half h = __float2half_rn(v);
        __half l = __float2half_rn(v - __half2float(h));
        int o = n * 136 + k;
        g_img[IMG_WH + o] = h;
        g_img[IMG_WH + 17408 + o] = l;
    } else if (idx < 90112) {               // E tiles
        int j = idx - 24576;
        int g = j >> 7, d = j & 127;
        int t = g >> 7, c = g & 127;
        float v = emb[g * H_DIM + d];
        __half h = __float2half_rn(v);
        __half l = __float2half_rn(v - __half2float(h));
        int o = c * 136 + d;
        g_img[IMG_E + t * 34816 + o] = h;
        g_img[IMG_E + t * 34816 + 17408 + o] = l;
    }
}

// ===================== kernel 3: fused main =====================
// SMEM byte map:
#define OFF_B1   0        // float[128]
#define OFF_BH   512
#define OFF_VV   1024     // float[128][2]
#define OFF_EE   2048     // float[512]
#define OFF_CD   4096     // float[128][4]
#define OFF_CI   6144     // int[128][4]
#define REG_A    8192     // 73728: input hi|lo(+18432) p144; W1 hi(+36864)|lo(+55296); later x2 hi|lo(+34816) p272
#define REG_C    81920    // 69632: x1 hi|lo(+34816) p272; later E tiles 0,2
#define REG_D    151552   // 69632: Wh hi|lo(+34816) p272; later E tiles 1,3
#define SMEM_BYTES 221184

// 3-pass split GEMM over a 16x64 warp tile (4 bt column blocks of 16)
__device__ __forceinline__ void run_gemm4(int ksteps, u32 aH, u32 aL, u32 bH, u32 bL,
                                          int pitchA, int pitchB,
                                          int lane, int wrow, int cbase, float (*acc)[4])
{
    const u32 aoff = (u32)(wrow + (lane & 15)) * pitchA + (u32)(lane >> 4) * 16;
    const u32 boff = (u32)(cbase + (lane & 7) + ((lane >> 4) << 3)) * pitchB
                   + (u32)((lane >> 3) & 1) * 16;
    for (int ks = 0; ks < ksteps; ks++) {
        u32 ah[4], al[4];
        LDSM4(ah, aH + aoff + ks * 32);
        LDSM4(al, aL + aoff + ks * 32);
#pragma unroll
        for (int bt = 0; bt < 4; bt++) {
            u32 bh[4], bl[4];
            LDSM4(bh, bH + boff + (u32)bt * 16 * pitchB + ks * 32);
            mma16816(acc[2 * bt],     ah, bh[0], bh[1]);
            mma16816(acc[2 * bt + 1], ah, bh[2], bh[3]);
            mma16816(acc[2 * bt],     al, bh[0], bh[1]);
            mma16816(acc[2 * bt + 1], al, bh[2], bh[3]);
            LDSM4(bl, bL + boff + (u32)bt * 16 * pitchB + ks * 32);
            mma16816(acc[2 * bt],     ah, bl[0], bl[1]);
            mma16816(acc[2 * bt + 1], ah, bl[2], bl[3]);
        }
    }
}

__global__ __launch_bounds__(NTHREADS, 1)
void fused_kernel(const float* __restrict__ in,
                  const float* __restrict__ b1, const float* __restrict__ bh,
                  const float* __restrict__ emb,
                  float* __restrict__ out)
{
    extern __shared__ __align__(16) unsigned char smem[];
    const u32 sb = smem_u32(smem);
    char* sc = (char*)smem;

    const int tid   = threadIdx.x;
    const int wid   = tid >> 5;
    const int lane  = tid & 31;
    const int g     = lane >> 2;
    const int q     = lane & 3;
    const int wrow  = (wid & 7) * 16;      // row strip
    const int chalf = wid >> 3;            // column half
    const int cbase = chalf * 64;
    const int r1 = wrow + g, r2 = r1 + 8;
    const int rowBase = blockIdx.x * TM;

    float* sB1 = (float*)(sc + OFF_B1);
    float* sBH = (float*)(sc + OFF_BH);
    float* sVV = (float*)(sc + OFF_VV);
    float* sEE = (float*)(sc + OFF_EE);
    float* sCD = (float*)(sc + OFF_CD);
    int*   sCI = (int*)  (sc + OFF_CI);

    const char* gimg = (const char*)g_img;

    // ---------------- Stage 0: prefetch W1, Wh; split input ----------------
    for (int i = tid; i < 2304; i += NTHREADS)                    // W1 images
        cpa16(sb + REG_A + 36864 + i * 16, gimg + IMG_W1 * 2 + i * 16);
    CP_COMMIT();                                                  // group: W1
    for (int i = tid; i < 4352; i += NTHREADS)                    // Wh images
        cpa16(sb + REG_D + i * 16, gimg + IMG_WH * 2 + i * 16);
    CP_COMMIT();                                                  // group: Wh

    for (int p = tid; p < 128 * 32; p += NTHREADS) {              // input split
        int row = p >> 5, pc = p & 31;
        float2 v = *(const float2*)(in + (size_t)(rowBase + row) * S_DIM + 2 * pc);
        __half h0 = __float2half_rn(v.x);
        __half h1 = __float2half_rn(v.y);
        u32 o = (u32)row * 144 + (u32)pc * 4;
        *(u32*)(sc + REG_A + o)         = pkh(__half2float(h0), __half2float(h1));
        *(u32*)(sc + REG_A + 18432 + o) = pkh(v.x - __half2float(h0), v.y - __half2float(h1));
    }
    if (tid < 128) { sB1[tid] = b1[tid]; sBH[tid] = bh[tid]; }
    if (tid < 512) sEE[tid] = g_ee[tid];
    CP_WAIT(1);                                                   // W1 arrived
    __syncthreads();

    float acc[8][4];

    // ---------------- Stage 1: x1 = relu(in @ W1 + b1) ----------------
#pragma unroll
    for (int t = 0; t < 8; t++)
#pragma unroll
        for (int j = 0; j < 4; j++) acc[t][j] = 0.0f;
    run_gemm4(4, sb + REG_A, sb + REG_A + 18432,
              sb + REG_A + 36864, sb + REG_A + 55296, 144, 144, lane, wrow, cbase, acc);
#pragma unroll
    for (int t = 0; t < 8; t++) {
        int c = cbase + 8 * t + 2 * q;
        float z0 = fmaxf(acc[t][0] + sB1[c],     0.0f);
        float z1 = fmaxf(acc[t][1] + sB1[c + 1], 0.0f);
        float z2 = fmaxf(acc[t][2] + sB1[c],     0.0f);
        float z3 = fmaxf(acc[t][3] + sB1[c + 1], 0.0f);
        __half h0 = __float2half_rn(z0), h1 = __float2half_rn(z1);
        __half h2 = __float2half_rn(z2), h3 = __float2half_rn(z3);
        u32 o1 = (u32)r1 * 272 + (u32)c * 2;
        u32 o2 = (u32)r2 * 272 + (u32)c * 2;
        *(u32*)(sc + REG_C + o1)         = pkh(__half2float(h0), __half2float(h1));
        *(u32*)(sc + REG_C + o2)         = pkh(__half2float(h2), __half2float(h3));
        *(u32*)(sc + REG_C + 34816 + o1) = pkh(z0 - __half2float(h0), z1 - __half2float(h1));
        *(u32*)(sc + REG_C + 34816 + o2) = pkh(z2 - __half2float(h2), z3 - __half2float(h3));
    }
    CP_WAIT(0);                                                   // Wh arrived
    __syncthreads();

    // ---------------- Stage 2: x2 = relu(x1 @ Wh + bh) ----------------
#pragma unroll
    for (int t = 0; t < 8; t++)
#pragma unroll
        for (int j = 0; j < 4; j++) acc[t][j] = 0.0f;
    run_gemm4(8, sb + REG_C, sb + REG_C + 34816,
              sb + REG_D, sb + REG_D + 34816, 272, 272, lane, wrow, cbase, acc);
    __syncthreads();   // all MMA reads of x1 (REG_C) and Wh (REG_D) complete

    // prefetch E tiles 0, 1 into the now-free REG_C / REG_D
    for (int i = tid; i < 4352; i += NTHREADS)
        cpa16(sb + REG_C + i * 16, gimg + IMG_E * 2 + i * 16);
    CP_COMMIT();                                                  // group: E0
    for (int i = tid; i < 4352; i += NTHREADS)
        cpa16(sb + REG_D + i * 16, gimg + IMG_E * 2 + 69632 + i * 16);
    CP_COMMIT();                                                  // group: E1

    // stage 2 epilogue (overlaps E0/E1 fills)
    {
        float vp1 = 0.0f, vp2 = 0.0f;
#pragma unroll
        for (int t = 0; t < 8; t++) {
            int c = cbase + 8 * t + 2 * q;
            float z0 = fmaxf(acc[t][0] + sBH[c],     0.0f);
            float z1 = fmaxf(acc[t][1] + sBH[c + 1], 0.0f);
            float z2 = fmaxf(acc[t][2] + sBH[c],     0.0f);
            float z3 = fmaxf(acc[t][3] + sBH[c + 1], 0.0f);
            __half h0 = __float2half_rn(z0), h1 = __float2half_rn(z1);
            __half h2 = __float2half_rn(z2), h3 = __float2half_rn(z3);
            float fl0 = z0 - __half2float(h0), fl1 = z1 - __half2float(h1);
            float fl2 = z2 - __half2float(h2), fl3 = z3 - __half2float(h3);
            float x0 = __half2float(h0) + __half2float(__float2half_rn(fl0));
            float x1 = __half2float(h1) + __half2float(__float2half_rn(fl1));
            float x2 = __half2float(h2) + __half2float(__float2half_rn(fl2));
            float x3 = __half2float(h3) + __half2float(__float2half_rn(fl3));
            vp1 = fmaf(x0, x0, vp1); vp1 = fmaf(x1, x1, vp1);
            vp2 = fmaf(x2, x2, vp2); vp2 = fmaf(x3, x3, vp2);
            u32 o1 = (u32)r1 * 272 + (u32)c * 2;
            u32 o2 = (u32)r2 * 272 + (u32)c * 2;
            *(u32*)(sc + REG_A + o1)         = pkh(__half2float(h0), __half2float(h1));
            *(u32*)(sc + REG_A + o2)         = pkh(__half2float(h2), __half2float(h3));
            *(u32*)(sc + REG_A + 34816 + o1) = pkh(fl0, fl1);
            *(u32*)(sc + REG_A + 34816 + o2) = pkh(fl2, fl3);
        }
        vp1 += __shfl_xor_sync(0xFFFFFFFFu, vp1, 1);
        vp1 += __shfl_xor_sync(0xFFFFFFFFu, vp1, 2);
        vp2 += __shfl_xor_sync(0xFFFFFFFFu, vp2, 1);
        vp2 += __shfl_xor_sync(0xFFFFFFFFu, vp2, 2);
        if (q == 0) { sVV[r1 * 2 + chalf] = vp1; sVV[r2 * 2 + chalf] = vp2; }
    }
    __syncthreads();

    // ---------------- Score: 4 tiles, double-buffered ----------------
    const float vv1 = sVV[r1 * 2] + sVV[r1 * 2 + 1];
    const float vv2 = sVV[r2 * 2] + sVV[r2 * 2 + 1];
    float b1d1 = __int_as_float(0x7f800000), b2d1 = b1d1;
    float b1d2 = b1d1, b2d2 = b1d1;
    int b1i1 = 0, b2i1 = 0, b1i2 = 0, b2i2 = 0;

    for (int tile = 0; tile < 4; tile++) {
        if (tile == 3) { CP_WAIT(0); } else { CP_WAIT(1); }
        __syncthreads();
        u32 buf = (tile & 1) ? (sb + REG_D) : (sb + REG_C);

#pragma unroll
        for (int t = 0; t < 8; t++)
#pragma unroll
            for (int j = 0; j < 4; j++) acc[t][j] = 0.0f;
        run_gemm4(8, sb + REG_A, sb + REG_A + 34816,
                  buf, buf + 34816, 272, 272, lane, wrow, cbase, acc);

        int codeBase = tile * 128 + cbase;
#pragma unroll
        for (int t = 0; t < 8; t++) {
            int c = codeBase + 8 * t + 2 * q;
#pragma unroll
            for (int jj = 0; jj < 2; jj++) {
                int code = c + jj;
                float ee = sEE[code];
                float d1 = fmaf(-2.0f, acc[t][jj],     vv1) + ee;
                float d2 = fmaf(-2.0f, acc[t][2 + jj], vv2) + ee;
                if (d1 < b1d1) { b2d1 = b1d1; b2i1 = b1i1; b1d1 = d1; b1i1 = code; }
                else if (d1 < b2d1) { b2d1 = d1; b2i1 = code; }
                if (d2 < b1d2) { b2d2 = b1d2; b2i2 = b1i2; b1d2 = d2; b1i2 = code; }
                else if (d2 < b2d2) { b2d2 = d2; b2i2 = code; }
            }
        }
        __syncthreads();   // buffer reads complete before refill

        if (tile < 2) {
            u32 dst = (tile & 1) ? (sb + REG_D) : (sb + REG_C);
            const char* src = gimg + IMG_E * 2 + (tile + 2) * 69632;
            for (int i = tid; i < 4352; i += NTHREADS)
                cpa16(dst + i * 16, src + i * 16);
            CP_COMMIT();
        }
    }

    // ---------------- merge top-2 across q lanes (per row, per col-half) ----
#pragma unroll
    for (int m = 1; m <= 2; m <<= 1) {
        float o1 = __shfl_xor_sync(0xFFFFFFFFu, b1d1, m);
        int  oi1 = __shfl_xor_sync(0xFFFFFFFFu, b1i1, m);
        float o2 = __shfl_xor_sync(0xFFFFFFFFu, b2d1, m);
        int  oi2 = __shfl_xor_sync(0xFFFFFFFFu, b2i1, m);
        if (o1 < b1d1) { b2d1 = b1d1; b2i1 = b1i1; b1d1 = o1; b1i1 = oi1; }
        else if (o1 < b2d1) { b2d1 = o1; b2i1 = oi1; }
        if (o2 < b2d1) { b2d1 = o2; b2i1 = oi2; }
        float p1 = __shfl_xor_sync(0xFFFFFFFFu, b1d2, m);
        int  pi1 = __shfl_xor_sync(0xFFFFFFFFu, b1i2, m);
        float p2 = __shfl_xor_sync(0xFFFFFFFFu, b2d2, m);
        int  pi2 = __shfl_xor_sync(0xFFFFFFFFu, b2i2, m);
        if (p1 < b1d2) { b2d2 = b1d2; b2i2 = b1i2; b1d2 = p1; b1i2 = pi1; }
        else if (p1 < b2d2) { b2d2 = p1; b2i2 = pi1; }
        if (p2 < b2d2) { b2d2 = p2; b2i2 = pi2; }
    }
    if (q == 0) {
        sCD[r1 * 4 + chalf * 2]     = b1d1;  sCI[r1 * 4 + chalf * 2]     = b1i1;
        sCD[r1 * 4 + chalf * 2 + 1] = b2d1;  sCI[r1 * 4 + chalf * 2 + 1] = b2i1;
        sCD[r2 * 4 + chalf * 2]     = b1d2;  sCI[r2 * 4 + chalf * 2]     = b1i2;
        sCD[r2 * 4 + chalf * 2 + 1] = b2d2;  sCI[r2 * 4 + chalf * 2 + 1] = b2i2;
    }
    __syncthreads();

    // ---------------- candidates + exact fp32 re-check + output ----------------
    if (tid < TM) {
        int row = tid;
        float cd[4]; int ci[4];
#pragma unroll
        for (int j = 0; j < 4; j++) { cd[j] = sCD[row * 4 + j]; ci[j] = sCI[row * 4 + j]; }
        float mn = fminf(fminf(cd[0], cd[1]), fminf(cd[2], cd[3]));
        int cnt = 0; int cidx[4];
#pragma unroll
        for (int j = 0; j < 4; j++)
            if (cd[j] <= mn + MARGIN) cidx[cnt++] = ci[j];

        int bestI;
        if (cnt == 1) {
            bestI = cidx[0];     // unique winner within margin >> approx error
        } else {
            float dots[4] = {0.0f, 0.0f, 0.0f, 0.0f};
            float vx = 0.0f;
            for (int i = 0; i < 64; i++) {
                int w = (row + i) & 63;
                u32 hw = *(const u32*)(sc + REG_A + (u32)row * 272 + (u32)w * 4);
                u32 lw = *(const u32*)(sc + REG_A + 34816 + (u32)row * 272 + (u32)w * 4);
                __half2 hh = *reinterpret_cast<__half2*>(&hw);
                __half2 ll = *reinterpret_cast<__half2*>(&lw);
                float x0 = __half2float(hh.x) + __half2float(ll.x);
                float x1 = __half2float(hh.y) + __half2float(ll.y);
                vx = fmaf(x0, x0, vx);
                vx = fmaf(x1, x1, vx);
                for (int j = 0; j < cnt; j++) {
                    const float* ep = emb + (size_t)cidx[j] * H_DIM + 2 * w;
                    dots[j] = fmaf(x0, __ldg(ep),     dots[j]);
                    dots[j] = fmaf(x1, __ldg(ep + 1), dots[j]);
                }
            }
            float bestD = __int_as_float(0x7f800000);
            bestI = 0x7fffffff;
            for (int j = 0; j < cnt; j++) {
                float dd = __fadd_rn(__fsub_rn(vx, __fmul_rn(2.0f, dots[j])), sEE[cidx[j]]);
                if (dd < bestD || (dd == bestD && cidx[j] < bestI)) { bestD = dd; bestI = cidx[j]; }
            }
        }

        int gr = rowBase + row;
        float4 p0 = *(const float4*)(g_probs + bestI * A_DIM);
        float4 p1 = *(const float4*)(g_probs + bestI * A_DIM + 4);
        float4* po = (float4*)out;
        po[gr * 2 + 0] = p0;
        po[gr * 2 + 1] = p1;
        out[(size_t)N_ROWS * A_DIM + gr] = g_value[bestI];
    }
}

// ===================== launch =====================
extern "C" void kernel_launch(void* const* d_in, const int* in_sizes, int n_in,
                              void* d_out, int out_size)
{
    const float* inputs = (const float*)d_in[0];
    const float* W1  = (const float*)d_in[1];
    const float* b1  = (const float*)d_in[2];
    const float* Wh  = (const float*)d_in[3];
    const float* bh  = (const float*)d_in[4];
    const float* emb = (const float*)d_in[5];
    const float* Wa  = (const float*)d_in[6];
    const float* ba  = (const float*)d_in[7];
    const float* Wv  = (const float*)d_in[8];
    const float* bv  = (const float*)d_in[9];

    cudaFuncSetAttribute(fused_kernel,
                         cudaFuncAttributeMaxDynamicSharedMemorySize, SMEM_BYTES);

    precompute_tables<<<64, 256>>>(emb, Wa, ba, Wv, bv);
    prep_weights<<<352, 256>>>(W1, Wh, emb);
    fused_kernel<<<N_ROWS / TM, NTHREADS, SMEM_BYTES>>>(
        inputs, b1, bh, emb, (float*)d_out);
}